// round 16
// baseline (speedup 1.0000x reference)
#include <cuda_runtime.h>
#include <cstdint>

// ---------------------------------------------------------------------------
// GNNMLP round 15 = round 13 (best, 495.8us, free-running warps) + register
// diet for 16 warps/CTA.
//   R14 proved CTA-phase-sync REGRESSES (barriers kill warp interleaving);
//   reverted. R13 was latency-bound at 3 warps/SMSP because 168 regs filled
//   the RF. Fix: nn1 + hsum live in per-warp smem scratch (nn1 aliases the
//   RES A-tile slot, dead until phase 4) -> ~110 regs -> 16 warps, occ 25%.
//   Math identical: bf16 3-split mma.sync m16n8k16, warp-private 16-group
//   chunks, B-fragments prepacked in global.
// ---------------------------------------------------------------------------

#define G_TOT   131072
#define CHUNKS  8192          // G_TOT / 16
#define NW      16
#define THREADS 512

// 12 matrices x 4096 u32 frags: [term(2)][s(4)][j(8)][lane(32)][reg(2)]
__device__ uint32_t g_frag[12 * 4096];

// ---- helpers ---------------------------------------------------------------
__device__ __forceinline__ uint32_t smem_u32(const void* p) {
    uint32_t a;
    asm("{ .reg .u64 t; cvta.to.shared.u64 t, %1; cvt.u32.u64 %0, t; }"
        : "=r"(a) : "l"(p));
    return a;
}
__device__ __forceinline__ void sts32(uint32_t a, uint32_t v) {
    asm volatile("st.shared.b32 [%0], %1;" :: "r"(a), "r"(v));
}
__device__ __forceinline__ void sts64f(uint32_t a, float x, float y) {
    asm volatile("st.shared.v2.f32 [%0], {%1,%2};" :: "r"(a), "f"(x), "f"(y));
}
__device__ __forceinline__ float2 lds64f(uint32_t a) {
    float2 r;
    asm volatile("ld.shared.v2.f32 {%0,%1}, [%2];" : "=f"(r.x), "=f"(r.y) : "r"(a));
    return r;
}
__device__ __forceinline__ void ldmx4(uint32_t& r0, uint32_t& r1, uint32_t& r2,
                                      uint32_t& r3, uint32_t addr) {
    asm volatile("ldmatrix.sync.aligned.m8n8.x4.shared.b16 {%0,%1,%2,%3}, [%4];"
                 : "=r"(r0), "=r"(r1), "=r"(r2), "=r"(r3) : "r"(addr));
}
__device__ __forceinline__ void mma4(float* d, uint32_t a0, uint32_t a1,
                                     uint32_t a2, uint32_t a3,
                                     uint32_t b0, uint32_t b1) {
    asm volatile("mma.sync.aligned.m16n8k16.row.col.f32.bf16.bf16.f32 "
                 "{%0,%1,%2,%3},{%4,%5,%6,%7},{%8,%9},{%0,%1,%2,%3};"
                 : "+f"(d[0]), "+f"(d[1]), "+f"(d[2]), "+f"(d[3])
                 : "r"(a0), "r"(a1), "r"(a2), "r"(a3), "r"(b0), "r"(b1));
}
__device__ __forceinline__ void split_store(uint32_t AH, uint32_t AL,
                                            uint32_t off, float x, float y) {
    unsigned short hx, hy, lx, ly;
    asm("cvt.rn.bf16.f32 %0, %1;" : "=h"(hx) : "f"(x));
    asm("cvt.rn.bf16.f32 %0, %1;" : "=h"(hy) : "f"(y));
    float rx = x - __uint_as_float((uint32_t)hx << 16);
    float ry = y - __uint_as_float((uint32_t)hy << 16);
    asm("cvt.rn.bf16.f32 %0, %1;" : "=h"(lx) : "f"(rx));
    asm("cvt.rn.bf16.f32 %0, %1;" : "=h"(ly) : "f"(ry));
    sts32(AH + off, (uint32_t)hx | ((uint32_t)hy << 16));
    sts32(AL + off, (uint32_t)lx | ((uint32_t)ly << 16));
}

// ---- prep kernel: weights -> B-fragment-ordered bf16 hi/lo images ----------
__global__ void prep_frag(const float* Wp1, const float* Ws1, const float* Wn1,
                          const float* Wp2, const float* Ws2, const float* Wn2,
                          const float* MW1, const float* MW2, const float* MW3)
{
    int j = blockIdx.x * blockDim.x + threadIdx.x;
    if (j >= 12 * 4096) return;
    int m = j >> 12, e = j & 4095;
    int term = e >> 11, s = (e >> 9) & 3, jt = (e >> 6) & 7;
    int lane = (e >> 1) & 31, reg = e & 1;
    const float* src;
    switch (m) {
        case 0: src = Wp1; break;  case 1: src = Ws1; break;
        case 2: src = Wn1; break;  case 3: src = Wp2; break;
        case 4: src = Ws2; break;  case 5: src = Wn2; break;
        case 6: src = MW1; break;  case 7: src = MW1 + 4096; break;
        case 8: src = MW2; break;  case 9: src = MW2 + 4096; break;
        case 10: src = MW3; break; default: src = MW3 + 4096; break;
    }
    int k0 = s * 16 + (lane & 3) * 2 + reg * 8;
    int n  = jt * 8 + (lane >> 2);
    float x0 = src[k0 * 64 + n], x1 = src[(k0 + 1) * 64 + n];
    unsigned short h0, h1;
    asm("cvt.rn.bf16.f32 %0, %1;" : "=h"(h0) : "f"(x0));
    asm("cvt.rn.bf16.f32 %0, %1;" : "=h"(h1) : "f"(x1));
    if (term == 1) {
        float r0 = x0 - __uint_as_float((uint32_t)h0 << 16);
        float r1 = x1 - __uint_as_float((uint32_t)h1 << 16);
        asm("cvt.rn.bf16.f32 %0, %1;" : "=h"(h0) : "f"(r0));
        asm("cvt.rn.bf16.f32 %0, %1;" : "=h"(h1) : "f"(r1));
    }
    g_frag[j] = (uint32_t)h0 | ((uint32_t)h1 << 16);
}

// ---- GEMM [16,64]x[64,64] with 3-split, acc[32] fp32 (D-frag layout) -------
__device__ __forceinline__ void gemm8(float* acc, uint32_t AH, uint32_t AL,
                                      const uint32_t* __restrict__ fb,
                                      int lane, bool zero)
{
    if (zero) {
        #pragma unroll
        for (int i = 0; i < 32; i++) acc[i] = 0.f;
    }
    #pragma unroll
    for (int s = 0; s < 4; s++) {
        uint32_t ad = (uint32_t)((lane & 15) * 144 + s * 32 + (lane >> 4) * 16);
        uint32_t aH0, aH1, aH2, aH3, aL0, aL1, aL2, aL3;
        ldmx4(aH0, aH1, aH2, aH3, AH + ad);
        ldmx4(aL0, aL1, aL2, aL3, AL + ad);
        #pragma unroll
        for (int jn = 0; jn < 8; jn++) {
            uint2 bh = *(const uint2*)(fb + s * 512 + jn * 64 + lane * 2);
            uint2 bl = *(const uint2*)(fb + 2048 + s * 512 + jn * 64 + lane * 2);
            mma4(acc + jn * 4, aH0, aH1, aH2, aH3, bh.x, bh.y);
            mma4(acc + jn * 4, aH0, aH1, aH2, aH3, bl.x, bl.y);
            mma4(acc + jn * 4, aL0, aL1, aL2, aL3, bh.x, bh.y);
        }
    }
}

// store D-layout regs v[32] into A tile (bf16 hi/lo)
__device__ __forceinline__ void stageD(uint32_t AH, uint32_t AL,
                                       const float* v, int lane)
{
    int r = lane >> 2, q = (lane & 3) * 2;
    #pragma unroll
    for (int j = 0; j < 8; j++) {
        uint32_t c = j * 8 + q;
        split_store(AH, AL, (uint32_t)((r * 72 + c) * 2),       v[j*4],   v[j*4+1]);
        split_store(AH, AL, (uint32_t)(((r + 8) * 72 + c) * 2), v[j*4+2], v[j*4+3]);
    }
}

// stage one agent's obs rows [16][64] into A tile
__device__ __forceinline__ void stage_obs(uint32_t AH, uint32_t AL,
                                          const float* __restrict__ src, int lane)
{
    int r = lane >> 1, f0 = (lane & 1) * 32;
    const float4* s4 = (const float4*)(src + (size_t)r * 384 + f0);
    uint32_t bo = (uint32_t)((r * 72 + f0) * 2);
    #pragma unroll
    for (int i = 0; i < 8; i++) {
        float4 v = s4[i];
        split_store(AH, AL, bo + i * 8,     v.x, v.y);
        split_store(AH, AL, bo + i * 8 + 4, v.z, v.w);
    }
}

struct Pm {
    const float *obs, *bp1, *b1, *bp2, *b2, *Mb1, *Mb2, *Mb3, *MW4, *Mb4;
    float* out;
};

extern __shared__ char smem[];
// smem: [0,4096) misc floats; warp w region (13312 B) at 4096 + w*13312:
//   AH0 +0 (2304) | AL0 +2304 | AH1 +4608 | AL1 +6912   (A tiles, 16x144B)
//   SC_NN = +4608 (4KB, ALIASES AH1/AL1: nn1 dead before RES is staged)
//   SC_HS = +9216 (4KB)
// scratch layout: float2 slot [idx][lane] at byte (idx*32+lane)*8, idx=0..15
#define WARP_BYTES 13312
#define SMEM_TOTAL (4096 + NW * WARP_BYTES)   // 217088

__global__ void __launch_bounds__(THREADS, 1) gnn_mma(Pm P)
{
    const int tid = threadIdx.x, lane = tid & 31, w = tid >> 5;
    float* miscf = (float*)smem;
    {
        const float* srcs[9] = {P.bp1, P.b1, P.bp2, P.b2, P.Mb1, P.Mb2, P.Mb3,
                                P.MW4, P.Mb4};
        const int offs[9] = {0, 64, 128, 192, 256, 384, 512, 640, 896};
        const int lens[9] = {64, 64, 64, 64, 128, 128, 128, 256, 4};
        for (int s = 0; s < 9; s++)
            for (int i = tid; i < lens[s]; i += THREADS)
                miscf[offs[s] + i] = srcs[s][i];
    }
    __syncthreads();

    const uint32_t sb = smem_u32(smem);
    const uint32_t WB  = sb + 4096 + w * WARP_BYTES;
    const uint32_t AH0 = WB, AL0 = WB + 2304, AH1 = WB + 4608, AL1 = WB + 6912;
    const uint32_t SCN = WB + 4608 + lane * 8;    // nn1 scratch (aliases AH1/AL1)
    const uint32_t SCH = WB + 9216 + lane * 8;    // hsum scratch
    const int q = (lane & 3) * 2;
    const int nwarp = gridDim.x * NW;

    for (int ch = blockIdx.x * NW + w; ch < CHUNKS; ch += nwarp) {
        const int gbase = ch * 16;
        const float* obsb = P.obs + (size_t)gbase * 384;
        float Nacc[32], acc[32];

        // ---- pass 1: N1 = max_a relu(obs_a @ Wp1 + bp1) ----
        #pragma unroll
        for (int i = 0; i < 32; i++) Nacc[i] = 0.f;
        for (int a = 0; a < 6; a++) {
            __syncwarp();
            stage_obs(AH0, AL0, obsb + a * 64, lane);
            __syncwarp();
            gemm8(acc, AH0, AL0, g_frag + 0 * 4096, lane, true);      // Wp1
            #pragma unroll
            for (int j = 0; j < 8; j++) {
                float2 b = *(const float2*)(miscf + 0 + j * 8 + q);   // bp1
                Nacc[j*4+0] = fmaxf(Nacc[j*4+0], acc[j*4+0] + b.x);
                Nacc[j*4+1] = fmaxf(Nacc[j*4+1], acc[j*4+1] + b.y);
                Nacc[j*4+2] = fmaxf(Nacc[j*4+2], acc[j*4+2] + b.x);
                Nacc[j*4+3] = fmaxf(Nacc[j*4+3], acc[j*4+3] + b.y);
            }
        }
        __syncwarp();
        stageD(AH0, AL0, Nacc, lane);
        __syncwarp();
        gemm8(acc, AH0, AL0, g_frag + 2 * 4096, lane, true);          // Wn1
        // nn1 -> smem scratch (fp32), and zero hsum scratch
        #pragma unroll
        for (int j = 0; j < 8; j++) {
            float2 b = *(const float2*)(miscf + 64 + j * 8 + q);      // b1
            sts64f(SCN + (2*j)   * 256, acc[j*4+0] + b.x, acc[j*4+1] + b.y);
            sts64f(SCN + (2*j+1) * 256, acc[j*4+2] + b.x, acc[j*4+3] + b.y);
            sts64f(SCH + (2*j)   * 256, 0.f, 0.f);
            sts64f(SCH + (2*j+1) * 256, 0.f, 0.f);
        }

        // ---- pass 2: h_a = tanh(obs_a@Ws1 + nn1); hsum RMW; N2 via h@Wp2 ----
        #pragma unroll
        for (int i = 0; i < 32; i++) Nacc[i] = 0.f;
        for (int a = 0; a < 6; a++) {
            __syncwarp();
            stage_obs(AH0, AL0, obsb + a * 64, lane);
            __syncwarp();
            gemm8(acc, AH0, AL0, g_frag + 1 * 4096, lane, true);      // Ws1
            #pragma unroll
            for (int j = 0; j < 8; j++) {
                float2 n0 = lds64f(SCN + (2*j)   * 256);
                float2 n1 = lds64f(SCN + (2*j+1) * 256);
                float h0 = tanhf(acc[j*4+0] + n0.x);
                float h1 = tanhf(acc[j*4+1] + n0.y);
                float h2 = tanhf(acc[j*4+2] + n1.x);
                float h3 = tanhf(acc[j*4+3] + n1.y);
                float2 s0 = lds64f(SCH + (2*j)   * 256);
                float2 s1 = lds64f(SCH + (2*j+1) * 256);
                sts64f(SCH + (2*j)   * 256, s0.x + h0, s0.y + h1);
                sts64f(SCH + (2*j+1) * 256, s1.x + h2, s1.y + h3);
                acc[j*4+0] = h0; acc[j*4+1] = h1;
                acc[j*4+2] = h2; acc[j*4+3] = h3;
            }
            __syncwarp();
            stageD(AH0, AL0, acc, lane);
            __syncwarp();
            gemm8(acc, AH0, AL0, g_frag + 3 * 4096, lane, true);      // Wp2
            #pragma unroll
            for (int j = 0; j < 8; j++) {
                float2 b = *(const float2*)(miscf + 128 + j * 8 + q); // bp2
                Nacc[j*4+0] = fmaxf(Nacc[j*4+0], acc[j*4+0] + b.x);
                Nacc[j*4+1] = fmaxf(Nacc[j*4+1], acc[j*4+1] + b.y);
                Nacc[j*4+2] = fmaxf(Nacc[j*4+2], acc[j*4+2] + b.x);
                Nacc[j*4+3] = fmaxf(Nacc[j*4+3], acc[j*4+3] + b.y);
            }
        }

        // ---- RES = (hsum/6)@Ws2 + N2@Wn2 + b2 ----
        __syncwarp();
        stageD(AH0, AL0, Nacc, lane);
        __syncwarp();
        gemm8(Nacc, AH0, AL0, g_frag + 5 * 4096, lane, true);         // Wn2 -> Nacc
        // load hsum/6 into acc, stage, then accumulate Ws2 on top of Nacc
        #pragma unroll
        for (int j = 0; j < 8; j++) {
            float2 s0 = lds64f(SCH + (2*j)   * 256);
            float2 s1 = lds64f(SCH + (2*j+1) * 256);
            acc[j*4+0] = s0.x * (1.f / 6.f); acc[j*4+1] = s0.y * (1.f / 6.f);
            acc[j*4+2] = s1.x * (1.f / 6.f); acc[j*4+3] = s1.y * (1.f / 6.f);
        }
        __syncwarp();
        stageD(AH0, AL0, acc, lane);
        __syncwarp();
        gemm8(Nacc, AH0, AL0, g_frag + 4 * 4096, lane, false);        // +Ws2
        #pragma unroll
        for (int j = 0; j < 8; j++) {
            float2 b = *(const float2*)(miscf + 192 + j * 8 + q);     // b2
            Nacc[j*4+0] += b.x; Nacc[j*4+1] += b.y;
            Nacc[j*4+2] += b.x; Nacc[j*4+3] += b.y;
        }
        __syncwarp();        // nn1 scratch dead; safe to overwrite AH1/AL1
        stageD(AH1, AL1, Nacc, lane);                                 // RES
        __syncwarp();

        // ---- per-type MLP + head ----
        float t0r0 = 0.f, t0r1 = 0.f, t0r2 = 0.f, t0r3 = 0.f;
        #pragma unroll
        for (int t = 0; t < 2; t++) {
            gemm8(acc, AH1, AL1, g_frag + (6 + t) * 4096, lane, true);   // MW1t
            #pragma unroll
            for (int j = 0; j < 8; j++) {
                float2 b = *(const float2*)(miscf + 256 + t * 64 + j * 8 + q);
                acc[j*4+0] = fmaxf(acc[j*4+0] + b.x, 0.f);
                acc[j*4+1] = fmaxf(acc[j*4+1] + b.y, 0.f);
                acc[j*4+2] = fmaxf(acc[j*4+2] + b.x, 0.f);
                acc[j*4+3] = fmaxf(acc[j*4+3] + b.y, 0.f);
            }
            __syncwarp();
            stageD(AH0, AL0, acc, lane);
            __syncwarp();
            gemm8(acc, AH0, AL0, g_frag + (8 + t) * 4096, lane, true);   // MW2t
            #pragma unroll
            for (int j = 0; j < 8; j++) {
                float2 b = *(const float2*)(miscf + 384 + t * 64 + j * 8 + q);
                acc[j*4+0] = fmaxf(acc[j*4+0] + b.x, 0.f);
                acc[j*4+1] = fmaxf(acc[j*4+1] + b.y, 0.f);
                acc[j*4+2] = fmaxf(acc[j*4+2] + b.x, 0.f);
                acc[j*4+3] = fmaxf(acc[j*4+3] + b.y, 0.f);
            }
            __syncwarp();
            stageD(AH0, AL0, acc, lane);
            __syncwarp();
            gemm8(acc, AH0, AL0, g_frag + (10 + t) * 4096, lane, true);  // MW3t
            float s0a = 0.f, s1a = 0.f, s0b = 0.f, s1b = 0.f;
            #pragma unroll
            for (int j = 0; j < 8; j++) {
                float2 b = *(const float2*)(miscf + 512 + t * 64 + j * 8 + q);
                float x0 = fmaxf(acc[j*4+0] + b.x, 0.f);
                float x1 = fmaxf(acc[j*4+1] + b.y, 0.f);
                float x2 = fmaxf(acc[j*4+2] + b.x, 0.f);
                float x3 = fmaxf(acc[j*4+3] + b.y, 0.f);
                float4 w4 = *(const float4*)(miscf + 640 + t * 128 + (j * 8 + q) * 2);
                s0a += x0 * w4.x + x1 * w4.z;
                s1a += x0 * w4.y + x1 * w4.w;
                s0b += x2 * w4.x + x3 * w4.z;
                s1b += x2 * w4.y + x3 * w4.w;
            }
            #pragma unroll
            for (int off = 1; off <= 2; off <<= 1) {
                s0a += __shfl_xor_sync(0xffffffffu, s0a, off);
                s1a += __shfl_xor_sync(0xffffffffu, s1a, off);
                s0b += __shfl_xor_sync(0xffffffffu, s0b, off);
                s1b += __shfl_xor_sync(0xffffffffu, s1b, off);
            }
            float m0 = miscf[896 + t * 2], m1 = miscf[897 + t * 2];
            s0a = tanhf(s0a + m0); s1a = tanhf(s1a + m1);
            s0b = tanhf(s0b + m0); s1b = tanhf(s1b + m1);
            if (t == 0) { t0r0 = s0a; t0r1 = s1a; t0r2 = s0b; t0r3 = s1b; }
            else if ((lane & 3) == 0) {
                int r = lane >> 2;
                float4* d0 = (float4*)(P.out + (size_t)(gbase + r) * 12);
                d0[0] = make_float4(t0r0, t0r1, t0r0, t0r1);
                d0[1] = make_float4(t0r0, t0r1, t0r0, t0r1);
                d0[2] = make_float4(t0r0, t0r1, s0a, s1a);
                float4* d1 = (float4*)(P.out + (size_t)(gbase + r + 8) * 12);
                d1[0] = make_float4(t0r2, t0r3, t0r2, t0r3);
                d1[1] = make_float4(t0r2, t0r3, t0r2, t0r3);
                d1[2] = make_float4(t0r2, t0r3, s0b, s1b);
            }
            __syncwarp();
        }
    }
}

extern "C" void kernel_launch(void* const* d_in, const int* in_sizes, int n_in,
                              void* d_out, int out_size)
{
    (void)in_sizes; (void)n_in; (void)out_size;
    const float* obs = (const float*)d_in[0];
    const float* Wp1 = (const float*)d_in[1];  const float* bp1 = (const float*)d_in[2];
    const float* Ws1 = (const float*)d_in[3];  const float* Wn1 = (const float*)d_in[4];
    const float* b1  = (const float*)d_in[5];
    const float* Wp2 = (const float*)d_in[6];  const float* bp2 = (const float*)d_in[7];
    const float* Ws2 = (const float*)d_in[8];  const float* Wn2 = (const float*)d_in[9];
    const float* b2  = (const float*)d_in[10];
    const float* MW1 = (const float*)d_in[11]; const float* Mb1 = (const float*)d_in[12];
    const float* MW2 = (const float*)d_in[13]; const float* Mb2 = (const float*)d_in[14];
    const float* MW3 = (const float*)d_in[15]; const float* Mb3 = (const float*)d_in[16];
    const float* MW4 = (const float*)d_in[17]; const float* Mb4 = (const float*)d_in[18];

    prep_frag<<<(12 * 4096 + 255) / 256, 256>>>(Wp1, Ws1, Wn1, Wp2, Ws2, Wn2,
                                                MW1, MW2, MW3);

    Pm P;
    P.obs = obs; P.bp1 = bp1; P.b1 = b1; P.bp2 = bp2; P.b2 = b2;
    P.Mb1 = Mb1; P.Mb2 = Mb2; P.Mb3 = Mb3; P.MW4 = MW4; P.Mb4 = Mb4;
    P.out = (float*)d_out;

    int dev = 0, nsm = 148;
    cudaGetDevice(&dev);
    cudaDeviceGetAttribute(&nsm, cudaDevAttrMultiProcessorCount, dev);

    cudaFuncSetAttribute(gnn_mma, cudaFuncAttributeMaxDynamicSharedMemorySize,
                         SMEM_TOTAL);
    gnn_mma<<<nsm, THREADS, SMEM_TOTAL>>>(P);
}

// round 17
// speedup vs baseline: 1.7367x; 1.7367x over previous
#include <cuda_runtime.h>
#include <cstdint>

// ---------------------------------------------------------------------------
// GNNMLP round 16 = round 13 skeleton (best: free-running warps, 168 regs,
// NW=12) + the 7 hottest B-fragment images resident in SMEM.
//   R14 (phase sync) and R15 (reg diet via smem scratch) both regressed;
//   R13's limiter is B-load latency (12 desynced warps thrash 192KB of
//   fragments through L1). Fix: Wp1/Ws1/Wp2/MW1x2/MW2x2 (22 of 27 gemm uses)
//   copied once into 114KB of smem -> 29-cyc LDS instead of L2-miss latency,
//   same wavefront count. Cold images (Wn1/Wn2/Ws2/MW3x2) stay in global.
// ---------------------------------------------------------------------------

#define G_TOT   131072
#define CHUNKS  8192          // G_TOT / 16
#define NW      12
#define THREADS 384

// 12 matrices x 4096 u32 frags: [term(2)][s(4)][j(8)][lane(32)][reg(2)]
// m: 0 Wp1, 1 Ws1, 2 Wn1, 3 Wp2, 4 Ws2, 5 Wn2, 6 MW1t0, 7 MW1t1,
//    8 MW2t0, 9 MW2t1, 10 MW3t0, 11 MW3t1
__device__ uint32_t g_frag[12 * 4096];

// ---- helpers ---------------------------------------------------------------
__device__ __forceinline__ uint32_t smem_u32(const void* p) {
    uint32_t a;
    asm("{ .reg .u64 t; cvta.to.shared.u64 t, %1; cvt.u32.u64 %0, t; }"
        : "=r"(a) : "l"(p));
    return a;
}
__device__ __forceinline__ void sts32(uint32_t a, uint32_t v) {
    asm volatile("st.shared.b32 [%0], %1;" :: "r"(a), "r"(v));
}
__device__ __forceinline__ void ldmx4(uint32_t& r0, uint32_t& r1, uint32_t& r2,
                                      uint32_t& r3, uint32_t addr) {
    asm volatile("ldmatrix.sync.aligned.m8n8.x4.shared.b16 {%0,%1,%2,%3}, [%4];"
                 : "=r"(r0), "=r"(r1), "=r"(r2), "=r"(r3) : "r"(addr));
}
__device__ __forceinline__ void mma4(float* d, uint32_t a0, uint32_t a1,
                                     uint32_t a2, uint32_t a3,
                                     uint32_t b0, uint32_t b1) {
    asm volatile("mma.sync.aligned.m16n8k16.row.col.f32.bf16.bf16.f32 "
                 "{%0,%1,%2,%3},{%4,%5,%6,%7},{%8,%9},{%0,%1,%2,%3};"
                 : "+f"(d[0]), "+f"(d[1]), "+f"(d[2]), "+f"(d[3])
                 : "r"(a0), "r"(a1), "r"(a2), "r"(a3), "r"(b0), "r"(b1));
}
__device__ __forceinline__ void split_store(uint32_t AH, uint32_t AL,
                                            uint32_t off, float x, float y) {
    unsigned short hx, hy, lx, ly;
    asm("cvt.rn.bf16.f32 %0, %1;" : "=h"(hx) : "f"(x));
    asm("cvt.rn.bf16.f32 %0, %1;" : "=h"(hy) : "f"(y));
    float rx = x - __uint_as_float((uint32_t)hx << 16);
    float ry = y - __uint_as_float((uint32_t)hy << 16);
    asm("cvt.rn.bf16.f32 %0, %1;" : "=h"(lx) : "f"(rx));
    asm("cvt.rn.bf16.f32 %0, %1;" : "=h"(ly) : "f"(ry));
    sts32(AH + off, (uint32_t)hx | ((uint32_t)hy << 16));
    sts32(AL + off, (uint32_t)lx | ((uint32_t)ly << 16));
}

// ---- prep kernel: weights -> B-fragment-ordered bf16 hi/lo images ----------
__global__ void prep_frag(const float* Wp1, const float* Ws1, const float* Wn1,
                          const float* Wp2, const float* Ws2, const float* Wn2,
                          const float* MW1, const float* MW2, const float* MW3)
{
    int j = blockIdx.x * blockDim.x + threadIdx.x;
    if (j >= 12 * 4096) return;
    int m = j >> 12, e = j & 4095;
    int term = e >> 11, s = (e >> 9) & 3, jt = (e >> 6) & 7;
    int lane = (e >> 1) & 31, reg = e & 1;
    const float* src;
    switch (m) {
        case 0: src = Wp1; break;  case 1: src = Ws1; break;
        case 2: src = Wn1; break;  case 3: src = Wp2; break;
        case 4: src = Ws2; break;  case 5: src = Wn2; break;
        case 6: src = MW1; break;  case 7: src = MW1 + 4096; break;
        case 8: src = MW2; break;  case 9: src = MW2 + 4096; break;
        case 10: src = MW3; break; default: src = MW3 + 4096; break;
    }
    int k0 = s * 16 + (lane & 3) * 2 + reg * 8;
    int n  = jt * 8 + (lane >> 2);
    float x0 = src[k0 * 64 + n], x1 = src[(k0 + 1) * 64 + n];
    unsigned short h0, h1;
    asm("cvt.rn.bf16.f32 %0, %1;" : "=h"(h0) : "f"(x0));
    asm("cvt.rn.bf16.f32 %0, %1;" : "=h"(h1) : "f"(x1));
    if (term == 1) {
        float r0 = x0 - __uint_as_float((uint32_t)h0 << 16);
        float r1 = x1 - __uint_as_float((uint32_t)h1 << 16);
        asm("cvt.rn.bf16.f32 %0, %1;" : "=h"(h0) : "f"(r0));
        asm("cvt.rn.bf16.f32 %0, %1;" : "=h"(h1) : "f"(r1));
    }
    g_frag[j] = (uint32_t)h0 | ((uint32_t)h1 << 16);
}

// ---- GEMM [16,64]x[64,64] 3-split, B from GLOBAL ---------------------------
__device__ __forceinline__ void gemm8(float* acc, uint32_t AH, uint32_t AL,
                                      const uint32_t* __restrict__ fb,
                                      int lane, bool zero)
{
    if (zero) {
        #pragma unroll
        for (int i = 0; i < 32; i++) acc[i] = 0.f;
    }
    #pragma unroll
    for (int s = 0; s < 4; s++) {
        uint32_t ad = (uint32_t)((lane & 15) * 144 + s * 32 + (lane >> 4) * 16);
        uint32_t aH0, aH1, aH2, aH3, aL0, aL1, aL2, aL3;
        ldmx4(aH0, aH1, aH2, aH3, AH + ad);
        ldmx4(aL0, aL1, aL2, aL3, AL + ad);
        #pragma unroll
        for (int jn = 0; jn < 8; jn++) {
            uint2 bh = *(const uint2*)(fb + s * 512 + jn * 64 + lane * 2);
            uint2 bl = *(const uint2*)(fb + 2048 + s * 512 + jn * 64 + lane * 2);
            mma4(acc + jn * 4, aH0, aH1, aH2, aH3, bh.x, bh.y);
            mma4(acc + jn * 4, aH0, aH1, aH2, aH3, bl.x, bl.y);
            mma4(acc + jn * 4, aL0, aL1, aL2, aL3, bh.x, bh.y);
        }
    }
}

// ---- GEMM [16,64]x[64,64] 3-split, B from SMEM (byte addr of image) --------
__device__ __forceinline__ void gemm8s(float* acc, uint32_t AH, uint32_t AL,
                                       uint32_t fb, int lane, bool zero)
{
    if (zero) {
        #pragma unroll
        for (int i = 0; i < 32; i++) acc[i] = 0.f;
    }
    #pragma unroll
    for (int s = 0; s < 4; s++) {
        uint32_t ad = (uint32_t)((lane & 15) * 144 + s * 32 + (lane >> 4) * 16);
        uint32_t aH0, aH1, aH2, aH3, aL0, aL1, aL2, aL3;
        ldmx4(aH0, aH1, aH2, aH3, AH + ad);
        ldmx4(aL0, aL1, aL2, aL3, AL + ad);
        #pragma unroll
        for (int jn = 0; jn < 8; jn++) {
            uint32_t off = (uint32_t)((s * 512 + jn * 64 + lane * 2) * 4);
            uint32_t bh0, bh1, bl0, bl1;
            asm volatile("ld.shared.v2.u32 {%0,%1}, [%2];"
                         : "=r"(bh0), "=r"(bh1) : "r"(fb + off));
            asm volatile("ld.shared.v2.u32 {%0,%1}, [%2];"
                         : "=r"(bl0), "=r"(bl1) : "r"(fb + 8192 + off));
            mma4(acc + jn * 4, aH0, aH1, aH2, aH3, bh0, bh1);
            mma4(acc + jn * 4, aH0, aH1, aH2, aH3, bl0, bl1);
            mma4(acc + jn * 4, aL0, aL1, aL2, aL3, bh0, bh1);
        }
    }
}

// store D-layout regs v[32] into A tile (bf16 hi/lo)
__device__ __forceinline__ void stageD(uint32_t AH, uint32_t AL,
                                       const float* v, int lane)
{
    int r = lane >> 2, q = (lane & 3) * 2;
    #pragma unroll
    for (int j = 0; j < 8; j++) {
        uint32_t c = j * 8 + q;
        split_store(AH, AL, (uint32_t)((r * 72 + c) * 2),       v[j*4],   v[j*4+1]);
        split_store(AH, AL, (uint32_t)(((r + 8) * 72 + c) * 2), v[j*4+2], v[j*4+3]);
    }
}

// stage one agent's obs rows [16][64] into A tile
__device__ __forceinline__ void stage_obs(uint32_t AH, uint32_t AL,
                                          const float* __restrict__ src, int lane)
{
    int r = lane >> 1, f0 = (lane & 1) * 32;
    const float4* s4 = (const float4*)(src + (size_t)r * 384 + f0);
    uint32_t bo = (uint32_t)((r * 72 + f0) * 2);
    #pragma unroll
    for (int i = 0; i < 8; i++) {
        float4 v = s4[i];
        split_store(AH, AL, bo + i * 8,     v.x, v.y);
        split_store(AH, AL, bo + i * 8 + 4, v.z, v.w);
    }
}

struct Pm {
    const float *obs, *bp1, *b1, *bp2, *b2, *Mb1, *Mb2, *Mb3, *MW4, *Mb4;
    float* out;
};

extern __shared__ char smem[];
// smem layout (bytes):
//   [0, 4096)                   misc floats
//   [4096, 4096+7*16384)        7 hot B-images: 0 Wp1, 1 Ws1, 2 Wp2,
//                               3 MW1t0, 4 MW1t1, 5 MW2t0, 6 MW2t1
//   [118784, +w*9216)           warp tiles: AH0|AL0|AH1|AL1 (16x144B each)
#define SM_BIMG 4096
#define SM_WARP (4096 + 7 * 16384)               // 118784
#define SMEM_TOTAL (SM_WARP + NW * 9216)         // 229376 <= 232448

__global__ void __launch_bounds__(THREADS, 1) gnn_mma(Pm P)
{
    const int tid = threadIdx.x, lane = tid & 31, w = tid >> 5;
    float* miscf = (float*)smem;
    {
        const float* srcs[9] = {P.bp1, P.b1, P.bp2, P.b2, P.Mb1, P.Mb2, P.Mb3,
                                P.MW4, P.Mb4};
        const int offs[9] = {0, 64, 128, 192, 256, 384, 512, 640, 896};
        const int lens[9] = {64, 64, 64, 64, 128, 128, 128, 256, 4};
        for (int s = 0; s < 9; s++)
            for (int i = tid; i < lens[s]; i += THREADS)
                miscf[offs[s] + i] = srcs[s][i];
    }
    // copy 7 hot B-images to smem (g_frag m -> smem slot): {0,1,3,6,7,8,9}
    {
        const int map[7] = {0, 1, 3, 6, 7, 8, 9};
        float4* d4 = (float4*)(smem + SM_BIMG);
        #pragma unroll 1
        for (int s = 0; s < 7; s++) {
            const float4* s4 = (const float4*)(g_frag + map[s] * 4096);
            for (int i = tid; i < 1024; i += THREADS)
                d4[s * 1024 + i] = s4[i];
        }
    }
    __syncthreads();

    const uint32_t sb = smem_u32(smem);
    const uint32_t BI = sb + SM_BIMG;
    const uint32_t WB  = sb + SM_WARP + w * 9216;
    const uint32_t AH0 = WB, AL0 = WB + 2304, AH1 = WB + 4608, AL1 = WB + 6912;
    const int q = (lane & 3) * 2;
    const int nwarp = gridDim.x * NW;

    for (int ch = blockIdx.x * NW + w; ch < CHUNKS; ch += nwarp) {
        const int gbase = ch * 16;
        const float* obsb = P.obs + (size_t)gbase * 384;
        float Nacc[32], nn1[32], hsum[32], acc[32];

        // ---- pass 1: N1 = max_a relu(obs_a @ Wp1 + bp1) ----
        #pragma unroll
        for (int i = 0; i < 32; i++) Nacc[i] = 0.f;
        for (int a = 0; a < 6; a++) {
            __syncwarp();
            stage_obs(AH0, AL0, obsb + a * 64, lane);
            __syncwarp();
            gemm8s(acc, AH0, AL0, BI + 0 * 16384, lane, true);        // Wp1 (smem)
            #pragma unroll
            for (int j = 0; j < 8; j++) {
                float2 b = *(const float2*)(miscf + 0 + j * 8 + q);   // bp1
                Nacc[j*4+0] = fmaxf(Nacc[j*4+0], acc[j*4+0] + b.x);
                Nacc[j*4+1] = fmaxf(Nacc[j*4+1], acc[j*4+1] + b.y);
                Nacc[j*4+2] = fmaxf(Nacc[j*4+2], acc[j*4+2] + b.x);
                Nacc[j*4+3] = fmaxf(Nacc[j*4+3], acc[j*4+3] + b.y);
            }
        }
        __syncwarp();
        stageD(AH0, AL0, Nacc, lane);
        __syncwarp();
        gemm8(acc, AH0, AL0, g_frag + 2 * 4096, lane, true);          // Wn1 (glob)
        #pragma unroll
        for (int j = 0; j < 8; j++) {
            float2 b = *(const float2*)(miscf + 64 + j * 8 + q);      // b1
            nn1[j*4+0] = acc[j*4+0] + b.x;
            nn1[j*4+1] = acc[j*4+1] + b.y;
            nn1[j*4+2] = acc[j*4+2] + b.x;
            nn1[j*4+3] = acc[j*4+3] + b.y;
        }

        // ---- pass 2: h_a = tanh(obs_a@Ws1 + nn1); hsum; N2 via h_a@Wp2 ----
        #pragma unroll
        for (int i = 0; i < 32; i++) { hsum[i] = 0.f; Nacc[i] = 0.f; }
        for (int a = 0; a < 6; a++) {
            __syncwarp();
            stage_obs(AH0, AL0, obsb + a * 64, lane);
            __syncwarp();
            gemm8s(acc, AH0, AL0, BI + 1 * 16384, lane, true);        // Ws1 (smem)
            #pragma unroll
            for (int i = 0; i < 32; i++) {
                float h = tanhf(acc[i] + nn1[i]);
                hsum[i] += h; acc[i] = h;
            }
            __syncwarp();
            stageD(AH0, AL0, acc, lane);
            __syncwarp();
            gemm8s(acc, AH0, AL0, BI + 2 * 16384, lane, true);        // Wp2 (smem)
            #pragma unroll
            for (int j = 0; j < 8; j++) {
                float2 b = *(const float2*)(miscf + 128 + j * 8 + q); // bp2
                Nacc[j*4+0] = fmaxf(Nacc[j*4+0], acc[j*4+0] + b.x);
                Nacc[j*4+1] = fmaxf(Nacc[j*4+1], acc[j*4+1] + b.y);
                Nacc[j*4+2] = fmaxf(Nacc[j*4+2], acc[j*4+2] + b.x);
                Nacc[j*4+3] = fmaxf(Nacc[j*4+3], acc[j*4+3] + b.y);
            }
        }
        // ---- RES = (hsum/6)@Ws2 + N2@Wn2 + b2 ----
        __syncwarp();
        stageD(AH0, AL0, Nacc, lane);
        __syncwarp();
        gemm8(acc, AH0, AL0, g_frag + 5 * 4096, lane, true);          // Wn2 (glob)
        #pragma unroll
        for (int i = 0; i < 32; i++) hsum[i] *= (1.f / 6.f);
        __syncwarp();
        stageD(AH0, AL0, hsum, lane);
        __syncwarp();
        gemm8(acc, AH0, AL0, g_frag + 4 * 4096, lane, false);         // +Ws2 (glob)
        #pragma unroll
        for (int j = 0; j < 8; j++) {
            float2 b = *(const float2*)(miscf + 192 + j * 8 + q);     // b2
            hsum[j*4+0] = acc[j*4+0] + b.x;   // hsum now holds RES
            hsum[j*4+1] = acc[j*4+1] + b.y;
            hsum[j*4+2] = acc[j*4+2] + b.x;
            hsum[j*4+3] = acc[j*4+3] + b.y;
        }
        __syncwarp();
        stageD(AH1, AL1, hsum, lane);                                 // RES
        __syncwarp();

        // ---- per-type MLP + head ----
        float t0r0 = 0.f, t0r1 = 0.f, t0r2 = 0.f, t0r3 = 0.f;
        #pragma unroll
        for (int t = 0; t < 2; t++) {
            gemm8s(acc, AH1, AL1, BI + (3 + t) * 16384, lane, true);     // MW1t (smem)
            #pragma unroll
            for (int j = 0; j < 8; j++) {
                float2 b = *(const float2*)(miscf + 256 + t * 64 + j * 8 + q);
                acc[j*4+0] = fmaxf(acc[j*4+0] + b.x, 0.f);
                acc[j*4+1] = fmaxf(acc[j*4+1] + b.y, 0.f);
                acc[j*4+2] = fmaxf(acc[j*4+2] + b.x, 0.f);
                acc[j*4+3] = fmaxf(acc[j*4+3] + b.y, 0.f);
            }
            __syncwarp();
            stageD(AH0, AL0, acc, lane);
            __syncwarp();
            gemm8s(acc, AH0, AL0, BI + (5 + t) * 16384, lane, true);     // MW2t (smem)
            #pragma unroll
            for (int j = 0; j < 8; j++) {
                float2 b = *(const float2*)(miscf + 384 + t * 64 + j * 8 + q);
                acc[j*4+0] = fmaxf(acc[j*4+0] + b.x, 0.f);
                acc[j*4+1] = fmaxf(acc[j*4+1] + b.y, 0.f);
                acc[j*4+2] = fmaxf(acc[j*4+2] + b.x, 0.f);
                acc[j*4+3] = fmaxf(acc[j*4+3] + b.y, 0.f);
            }
            __syncwarp();
            stageD(AH0, AL0, acc, lane);
            __syncwarp();
            gemm8(acc, AH0, AL0, g_frag + (10 + t) * 4096, lane, true);  // MW3t (glob)
            float s0a = 0.f, s1a = 0.f, s0b = 0.f, s1b = 0.f;
            #pragma unroll
            for (int j = 0; j < 8; j++) {
                float2 b = *(const float2*)(miscf + 512 + t * 64 + j * 8 + q);
                float x0 = fmaxf(acc[j*4+0] + b.x, 0.f);
                float x1 = fmaxf(acc[j*4+1] + b.y, 0.f);
                float x2 = fmaxf(acc[j*4+2] + b.x, 0.f);
                float x3 = fmaxf(acc[j*4+3] + b.y, 0.f);
                float4 w4 = *(const float4*)(miscf + 640 + t * 128 + (j * 8 + q) * 2);
                s0a += x0 * w4.x + x1 * w4.z;
                s1a += x0 * w4.y + x1 * w4.w;
                s0b += x2 * w4.x + x3 * w4.z;
                s1b += x2 * w4.y + x3 * w4.w;
            }
            #pragma unroll
            for (int off = 1; off <= 2; off <<= 1) {
                s0a += __shfl_xor_sync(0xffffffffu, s0a, off);
                s1a += __shfl_xor_sync(0xffffffffu, s1a, off);
                s0b += __shfl_xor_sync(0xffffffffu, s0b, off);
                s1b += __shfl_xor_sync(0xffffffffu, s1b, off);
            }
            float m0 = miscf[896 + t * 2], m1 = miscf[897 + t * 2];
            s0a = tanhf(s0a + m0); s1a = tanhf(s1a + m1);
            s0b = tanhf(s0b + m0); s1b = tanhf(s1b + m1);
            if (t == 0) { t0r0 = s0a; t0r1 = s1a; t0r2 = s0b; t0r3 = s1b; }
            else if ((lane & 3) == 0) {
                int r = lane >> 2;
                float4* d0 = (float4*)(P.out + (size_t)(gbase + r) * 12);
                d0[0] = make_float4(t0r0, t0r1, t0r0, t0r1);
                d0[1] = make_float4(t0r0, t0r1, t0r0, t0r1);
                d0[2] = make_float4(t0r0, t0r1, s0a, s1a);
                float4* d1 = (float4*)(P.out + (size_t)(gbase + r + 8) * 12);
                d1[0] = make_float4(t0r2, t0r3, t0r2, t0r3);
                d1[1] = make_float4(t0r2, t0r3, t0r2, t0r3);
                d1[2] = make_float4(t0r2, t0r3, s0b, s1b);
            }
            __syncwarp();
        }
    }
}

extern "C" void kernel_launch(void* const* d_in, const int* in_sizes, int n_in,
                              void* d_out, int out_size)
{
    (void)in_sizes; (void)n_in; (void)out_size;
    const float* obs = (const float*)d_in[0];
    const float* Wp1 = (const float*)d_in[1];  const float* bp1 = (const float*)d_in[2];
    const float* Ws1 = (const float*)d_in[3];  const float* Wn1 = (const float*)d_in[4];
    const float* b1  = (const float*)d_in[5];
    const float* Wp2 = (const float*)d_in[6];  const float* bp2 = (const float*)d_in[7];
    const float* Ws2 = (const float*)d_in[8];  const float* Wn2 = (const float*)d_in[9];
    const float* b2  = (const float*)d_in[10];
    const float* MW1 = (const float*)d_in[11]; const float* Mb1 = (const float*)d_in[12];
    const float* MW2 = (const float*)d_in[13]; const float* Mb2 = (const float*)d_in[14];
    const float* MW3 = (const float*)d_in[15]; const float* Mb3 = (const float*)d_in[16];
    const float* MW4 = (const float*)d_in[17]; const float* Mb4 = (const float*)d_in[18];

    prep_frag<<<(12 * 4096 + 255) / 256, 256>>>(Wp1, Ws1, Wn1, Wp2, Ws2, Wn2,
                                                MW1, MW2, MW3);

    Pm P;
    P.obs = obs; P.bp1 = bp1; P.b1 = b1; P.bp2 = bp2; P.b2 = b2;
    P.Mb1 = Mb1; P.Mb2 = Mb2; P.Mb3 = Mb3; P.MW4 = MW4; P.Mb4 = Mb4;
    P.out = (float*)d_out;

    int dev = 0, nsm = 148;
    cudaGetDevice(&dev);
    cudaDeviceGetAttribute(&nsm, cudaDevAttrMultiProcessorCount, dev);

    cudaFuncSetAttribute(gnn_mma, cudaFuncAttributeMaxDynamicSharedMemorySize,
                         SMEM_TOTAL);
    gnn_mma<<<nsm, THREADS, SMEM_TOTAL>>>(P);
}